// round 5
// baseline (speedup 1.0000x reference)
#include <cuda_runtime.h>
#include <cstdint>
#include <cstddef>

// Problem constants
#define NTOK 8192          // B*S tokens
#define HD   2048          // hidden
#define NEXP 8             // experts
#define FD   1408          // moe inter dim
#define CAP  8192          // per-expert row capacity (worst case all tokens)

// GEMM tiling
#define AS    36           // smem row stride (32 + 4 pad -> conflict-free frag loads)
#define ABUF  (128 * AS)
#define BBUF  (64 * AS)
#define KT1   (HD / 32)    // 64 k-tiles for gate/up
#define KT2   (FD / 32)    // 44 k-tiles for down
#define SMEM1 ((2 * ABUF + 4 * BBUF) * 4 + 512)
#define SMEM2 ((2 * ABUF + 2 * BBUF) * 4 + 1024)

// Scratch (device globals: allocation-free rule)
__device__ int   g_count[NEXP];
__device__ int   g_slots[NEXP * CAP];            // slot id = token*2 + k
__device__ float g_slot_w[NTOK * 2];
__device__ float g_hbuf[(size_t)NTOK * 2 * FD];  // swiglu output per slot
__device__ float g_sout[(size_t)NTOK * 2 * HD];  // weighted down output per slot

// ---------------------------------------------------------------------------
// helpers
// ---------------------------------------------------------------------------
__device__ __forceinline__ uint32_t to_tf32(float f) {
  uint32_t u;
  asm("cvt.rna.tf32.f32 %0, %1;" : "=r"(u) : "f"(f));
  return u;
}

__device__ __forceinline__ void mma_tf32(float* c, const uint32_t* a, const uint32_t* b) {
  asm volatile(
      "mma.sync.aligned.m16n8k8.row.col.f32.tf32.tf32.f32 "
      "{%0,%1,%2,%3}, {%4,%5,%6,%7}, {%8,%9}, {%0,%1,%2,%3};\n"
      : "+f"(c[0]), "+f"(c[1]), "+f"(c[2]), "+f"(c[3])
      : "r"(a[0]), "r"(a[1]), "r"(a[2]), "r"(a[3]), "r"(b[0]), "r"(b[1]));
}

__device__ __forceinline__ void cp16(void* sdst, const void* gsrc, int src_bytes) {
  uint32_t sa = (uint32_t)__cvta_generic_to_shared(sdst);
  asm volatile("cp.async.cg.shared.global [%0], [%1], 16, %2;\n"
               :: "r"(sa), "l"(gsrc), "r"(src_bytes));
}
__device__ __forceinline__ void cp_commit() {
  asm volatile("cp.async.commit_group;\n");
}

// ---------------------------------------------------------------------------
// 0) zero expert counters
// ---------------------------------------------------------------------------
__global__ void zero_counts_kernel() {
  if (threadIdx.x < NEXP) g_count[threadIdx.x] = 0;
}

// ---------------------------------------------------------------------------
// 1) router: logits (exact fp32), top-2, normalized weights, slot assignment.
//    Atomic ordering only permutes rows within an expert; each row's math is
//    independent and scattered back by slot id -> bit-deterministic output.
// ---------------------------------------------------------------------------
__global__ void __launch_bounds__(256) router_kernel(
    const float* __restrict__ x, const float* __restrict__ rw) {
  __shared__ float4 xs[HD / 4];
  __shared__ float logits[NEXP];
  const int t = blockIdx.x;
  const float4* xr = (const float4*)(x + (size_t)t * HD);
  for (int i = threadIdx.x; i < HD / 4; i += 256) xs[i] = xr[i];
  __syncthreads();
  const int w = threadIdx.x >> 5, lane = threadIdx.x & 31;
  const float4* rw4 = (const float4*)(rw + w * HD);
  float acc = 0.f;
  for (int i = lane; i < HD / 4; i += 32) {
    float4 a = xs[i], b = rw4[i];
    acc += a.x * b.x + a.y * b.y + a.z * b.z + a.w * b.w;
  }
  #pragma unroll
  for (int off = 16; off > 0; off >>= 1) acc += __shfl_xor_sync(0xffffffffu, acc, off);
  if (lane == 0) logits[w] = acc;
  __syncthreads();
  if (threadIdx.x == 0) {
    int e0 = 0; float l0 = logits[0];
    #pragma unroll
    for (int e = 1; e < NEXP; e++) if (logits[e] > l0) { l0 = logits[e]; e0 = e; }
    int e1 = -1; float l1 = -3.4e38f;
    #pragma unroll
    for (int e = 0; e < NEXP; e++) if (e != e0 && logits[e] > l1) { l1 = logits[e]; e1 = e; }
    // topk(softmax) renormalized == 2-way softmax over the top-2 logits
    float p1 = __expf(l1 - l0);      // l0 >= l1
    float inv = 1.f / (1.f + p1);
    int pos0 = atomicAdd(&g_count[e0], 1);
    g_slots[e0 * CAP + pos0] = 2 * t;
    g_slot_w[2 * t] = inv;
    int pos1 = atomicAdd(&g_count[e1], 1);
    g_slots[e1 * CAP + pos1] = 2 * t + 1;
    g_slot_w[2 * t + 1] = p1 * inv;
  }
}

// ---------------------------------------------------------------------------
// 2) fused gate+up GEMM + SwiGLU.  C[128 x 64] per block, tf32 mma,
//    cp.async double-buffered, A rows gathered indirectly by token id.
// ---------------------------------------------------------------------------
__global__ void __launch_bounds__(256) gemm_gateup_kernel(
    const float* __restrict__ x,
    const float* __restrict__ gate_w,
    const float* __restrict__ up_w) {
  const int e = blockIdx.z;
  const int Ne = g_count[e];
  const int bm = blockIdx.y;
  if (bm * 128 >= Ne) return;
  const int bn = blockIdx.x;
  const int tid = threadIdx.x;

  extern __shared__ float sm[];
  float* Asm = sm;
  float* Bgm = sm + 2 * ABUF;
  float* Bum = Bgm + 2 * BBUF;
  int* slots = (int*)(Bum + 2 * BBUF);

  if (tid < 128) {
    int gr = bm * 128 + tid;
    slots[tid] = (gr < Ne) ? g_slots[e * CAP + gr] : -1;
  }
  __syncthreads();

  const int ar = tid >> 1;
  const int aj = (tid & 1) * 16;
  const int s_a = slots[ar];
  const float* gA = x + (size_t)((s_a >= 0) ? (s_a >> 1) : 0) * HD + aj;
  const int a_sz = (s_a >= 0) ? 16 : 0;
  const size_t wb = (size_t)e * FD * HD;

  const int wid = tid >> 5, lane = tid & 31;
  const int wm = wid & 3, wn = wid >> 2;
  const int lr = lane >> 2, lc = lane & 3;

  float cg[2][4][4], cu[2][4][4];
  #pragma unroll
  for (int i = 0; i < 2; i++)
    #pragma unroll
    for (int j = 0; j < 4; j++)
      #pragma unroll
      for (int q = 0; q < 4; q++) { cg[i][j][q] = 0.f; cu[i][j][q] = 0.f; }

  auto load_tile = [&](int kt, int buf) {
    const int k0 = kt * 32;
    float* dA = Asm + buf * ABUF + ar * AS + aj;
    const float* srcA = gA + k0;
    cp16(dA,      srcA,      a_sz);
    cp16(dA + 4,  srcA + 4,  a_sz);
    cp16(dA + 8,  srcA + 8,  a_sz);
    cp16(dA + 12, srcA + 12, a_sz);
    #pragma unroll
    for (int r2 = 0; r2 < 2; r2++) {
      int idx = tid * 2 + r2;
      int br = idx >> 3;
      int jj = (idx & 7) * 4;
      size_t go = wb + (size_t)(bn * 64 + br) * HD + k0 + jj;
      cp16(Bgm + buf * BBUF + br * AS + jj, gate_w + go, 16);
      cp16(Bum + buf * BBUF + br * AS + jj, up_w + go, 16);
    }
    cp_commit();
  };

  auto compute_tile = [&](int buf) {
    const float* Ab = Asm + buf * ABUF;
    const float* Gb = Bgm + buf * BBUF;
    const float* Ub = Bum + buf * BBUF;
    #pragma unroll
    for (int ks = 0; ks < 4; ks++) {
      const int kb = ks * 8 + lc;
      uint32_t af[2][4];
      #pragma unroll
      for (int i = 0; i < 2; i++) {
        const int r = wm * 32 + i * 16 + lr;
        af[i][0] = to_tf32(Ab[r * AS + kb]);
        af[i][1] = to_tf32(Ab[(r + 8) * AS + kb]);
        af[i][2] = to_tf32(Ab[r * AS + kb + 4]);
        af[i][3] = to_tf32(Ab[(r + 8) * AS + kb + 4]);
      }
      uint32_t bg[4][2], bu[4][2];
      #pragma unroll
      for (int j = 0; j < 4; j++) {
        const int n = wn * 32 + j * 8 + lr;
        bg[j][0] = to_tf32(Gb[n * AS + kb]);
        bg[j][1] = to_tf32(Gb[n * AS + kb + 4]);
        bu[j][0] = to_tf32(Ub[n * AS + kb]);
        bu[j][1] = to_tf32(Ub[n * AS + kb + 4]);
      }
      #pragma unroll
      for (int i = 0; i < 2; i++)
        #pragma unroll
        for (int j = 0; j < 4; j++) {
          mma_tf32(cg[i][j], af[i], bg[j]);
          mma_tf32(cu[i][j], af[i], bu[j]);
        }
    }
  };

  load_tile(0, 0);
  #pragma unroll 1
  for (int kt = 0; kt < KT1; kt++) {
    const int buf = kt & 1;
    if (kt + 1 < KT1) {
      load_tile(kt + 1, buf ^ 1);
      asm volatile("cp.async.wait_group 1;\n");
    } else {
      asm volatile("cp.async.wait_group 0;\n");
    }
    __syncthreads();
    compute_tile(buf);
    __syncthreads();
  }

  // SwiGLU epilogue -> hbuf[slot][F]
  #pragma unroll
  for (int i = 0; i < 2; i++)
    #pragma unroll
    for (int h = 0; h < 2; h++) {
      const int r = wm * 32 + i * 16 + h * 8 + lr;
      const int s = slots[r];
      if (s < 0) continue;
      float* orow = g_hbuf + (size_t)s * FD + bn * 64 + wn * 32 + lc * 2;
      #pragma unroll
      for (int j = 0; j < 4; j++) {
        float g0 = cg[i][j][h * 2], g1 = cg[i][j][h * 2 + 1];
        float u0 = cu[i][j][h * 2], u1 = cu[i][j][h * 2 + 1];
        float v0 = g0 * u0 / (1.f + __expf(-g0));
        float v1 = g1 * u1 / (1.f + __expf(-g1));
        *(float2*)(orow + j * 8) = make_float2(v0, v1);
      }
    }
}

// ---------------------------------------------------------------------------
// 3) down GEMM: sout[slot][H] = weight * (hbuf[slot] @ down_w[e]^T)
// ---------------------------------------------------------------------------
__global__ void __launch_bounds__(256) gemm_down_kernel(
    const float* __restrict__ down_w) {
  const int e = blockIdx.z;
  const int Ne = g_count[e];
  const int bm = blockIdx.y;
  if (bm * 128 >= Ne) return;
  const int bn = blockIdx.x;
  const int tid = threadIdx.x;

  extern __shared__ float sm[];
  float* Asm = sm;
  float* Bdm = sm + 2 * ABUF;
  int* slots = (int*)(Bdm + 2 * BBUF);
  float* wts = (float*)(slots + 128);

  if (tid < 128) {
    int gr = bm * 128 + tid;
    int s = (gr < Ne) ? g_slots[e * CAP + gr] : -1;
    slots[tid] = s;
    wts[tid] = (s >= 0) ? g_slot_w[s] : 0.f;
  }
  __syncthreads();

  const int ar = tid >> 1;
  const int aj = (tid & 1) * 16;
  const int s_a = slots[ar];
  const float* gA = g_hbuf + (size_t)((s_a >= 0) ? s_a : 0) * FD + aj;
  const int a_sz = (s_a >= 0) ? 16 : 0;
  const size_t wb = (size_t)e * HD * FD;

  const int wid = tid >> 5, lane = tid & 31;
  const int wm = wid & 3, wn = wid >> 2;
  const int lr = lane >> 2, lc = lane & 3;

  float cd[2][4][4];
  #pragma unroll
  for (int i = 0; i < 2; i++)
    #pragma unroll
    for (int j = 0; j < 4; j++)
      #pragma unroll
      for (int q = 0; q < 4; q++) cd[i][j][q] = 0.f;

  auto load_tile = [&](int kt, int buf) {
    const int k0 = kt * 32;
    float* dA = Asm + buf * ABUF + ar * AS + aj;
    const float* srcA = gA + k0;
    cp16(dA,      srcA,      a_sz);
    cp16(dA + 4,  srcA + 4,  a_sz);
    cp16(dA + 8,  srcA + 8,  a_sz);
    cp16(dA + 12, srcA + 12, a_sz);
    #pragma unroll
    for (int r2 = 0; r2 < 2; r2++) {
      int idx = tid * 2 + r2;
      int br = idx >> 3;
      int jj = (idx & 7) * 4;
      cp16(Bdm + buf * BBUF + br * AS + jj,
           down_w + wb + (size_t)(bn * 64 + br) * FD + k0 + jj, 16);
    }
    cp_commit();
  };

  auto compute_tile = [&](int buf) {
    const float* Ab = Asm + buf * ABUF;
    const float* Db = Bdm + buf * BBUF;
    #pragma unroll
    for (int ks = 0; ks < 4; ks++) {
      const int kb = ks * 8 + lc;
      uint32_t af[2][4];
      #pragma unroll
      for (int i = 0; i < 2; i++) {
        const int r = wm * 32 + i * 16 + lr;
        af[i][0] = to_tf32(Ab[r * AS + kb]);
        af[i][1] = to_tf32(Ab[(r + 8) * AS + kb]);
        af[i][2] = to_tf32(Ab[r * AS + kb + 4]);
        af[i][3] = to_tf32(Ab[(r + 8) * AS + kb + 4]);
      }
      uint32_t bd[4][2];
      #pragma unroll
      for (int j = 0; j < 4; j++) {
        const int n = wn * 32 + j * 8 + lr;
        bd[j][0] = to_tf32(Db[n * AS + kb]);
        bd[j][1] = to_tf32(Db[n * AS + kb + 4]);
      }
      #pragma unroll
      for (int i = 0; i < 2; i++)
        #pragma unroll
        for (int j = 0; j < 4; j++)
          mma_tf32(cd[i][j], af[i], bd[j]);
    }
  };

  load_tile(0, 0);
  #pragma unroll 1
  for (int kt = 0; kt < KT2; kt++) {
    const int buf = kt & 1;
    if (kt + 1 < KT2) {
      load_tile(kt + 1, buf ^ 1);
      asm volatile("cp.async.wait_group 1;\n");
    } else {
      asm volatile("cp.async.wait_group 0;\n");
    }
    __syncthreads();
    compute_tile(buf);
    __syncthreads();
  }

  #pragma unroll
  for (int i = 0; i < 2; i++)
    #pragma unroll
    for (int h = 0; h < 2; h++) {
      const int r = wm * 32 + i * 16 + h * 8 + lr;
      const int s = slots[r];
      if (s < 0) continue;
      const float wgt = wts[r];
      float* orow = g_sout + (size_t)s * HD + bn * 64 + wn * 32 + lc * 2;
      #pragma unroll
      for (int j = 0; j < 4; j++) {
        float v0 = cd[i][j][h * 2] * wgt;
        float v1 = cd[i][j][h * 2 + 1] * wgt;
        *(float2*)(orow + j * 8) = make_float2(v0, v1);
      }
    }
}

// ---------------------------------------------------------------------------
// 4) deterministic combine: out[t] = sout[2t] + sout[2t+1]
// ---------------------------------------------------------------------------
__global__ void __launch_bounds__(256) combine_kernel(float* __restrict__ out) {
  const int idx = blockIdx.x * 256 + threadIdx.x;   // float4 index
  const int t = idx >> 9;                           // HD/4 = 512
  const int h4 = idx & 511;
  const float4* s4 = (const float4*)g_sout;
  float4 a = s4[(size_t)(2 * t) * 512 + h4];
  float4 b = s4[(size_t)(2 * t + 1) * 512 + h4];
  ((float4*)out)[idx] = make_float4(a.x + b.x, a.y + b.y, a.z + b.z, a.w + b.w);
}

// ---------------------------------------------------------------------------
extern "C" void kernel_launch(void* const* d_in, const int* in_sizes, int n_in,
                              void* d_out, int out_size) {
  const float* x  = (const float*)d_in[0];  // hidden_states [4,2048,2048]
  const float* rw = (const float*)d_in[1];  // router_w [8,2048]
  const float* gw = (const float*)d_in[2];  // gate_w [8,1408,2048]
  const float* uw = (const float*)d_in[3];  // up_w   [8,1408,2048]
  const float* dw = (const float*)d_in[4];  // down_w [8,2048,1408]
  float* out = (float*)d_out;

  cudaFuncSetAttribute(gemm_gateup_kernel,
                       cudaFuncAttributeMaxDynamicSharedMemorySize, SMEM1);
  cudaFuncSetAttribute(gemm_down_kernel,
                       cudaFuncAttributeMaxDynamicSharedMemorySize, SMEM2);

  zero_counts_kernel<<<1, 32>>>();
  router_kernel<<<NTOK, 256>>>(x, rw);
  gemm_gateup_kernel<<<dim3(FD / 64, CAP / 128, NEXP), 256, SMEM1>>>(x, gw, uw);
  gemm_down_kernel<<<dim3(HD / 64, CAP / 128, NEXP), 256, SMEM2>>>(dw);
  combine_kernel<<<(NTOK * (HD / 4)) / 256, 256>>>(out);
}